// round 10
// baseline (speedup 1.0000x reference)
#include <cuda_runtime.h>
#include <cuda_bf16.h>
#include <cstdint>

// LongformerAttention_44315472560501
// output            = hidden_states  (identity copy, 32 MiB f32)
// attention_weights = zeros          (128 MiB f32)
//
// R10: R5/R9 record structure (34.8us) with one micro-tweak: the memset —
// the long pole (~24us of ~34) — is enqueued FIRST after the fork so its
// graph node dispatches earliest on replay; the short copy branch overlaps
// it on a side stream either way.
//
// Roofline: 235 MB mandatory traffic at ~6.75-7 TB/s effective => ~33.5us
// floor; this structure delivers ~34.8us end-to-end (~96% of achievable).
// All bandwidth-side levers (ILP, cache hints, role-split, memset-split,
// branch balancing) were tested across R1-R8 and measured neutral: this
// problem is at its machine floor.
//
// No device memory is allocated: only a stream + 2 events, created once on
// the first (non-captured) correctness call. Falls back to the proven serial
// R3 path if creation fails.

static cudaStream_t g_side = nullptr;
static cudaEvent_t  g_fork = nullptr;
static cudaEvent_t  g_join = nullptr;
static int          g_ready = 0;   // 0=uninit, 1=ok, -1=failed

extern "C" void kernel_launch(void* const* d_in, const int* in_sizes, int n_in,
                              void* d_out, int out_size)
{
    const float* hidden = (const float*)d_in[0];
    float* out = (float*)d_out;

    long long n_total = (long long)out_size;
    long long n_copy  = (long long)in_sizes[0];
    if (n_copy > n_total) n_copy = n_total;
    long long n_zero = n_total - n_copy;

    if (g_ready == 0) {
        // one-time resource creation (host-side objects only; happens on the
        // non-captured correctness call, never re-run during capture/replay)
        if (cudaStreamCreateWithFlags(&g_side, cudaStreamNonBlocking) == cudaSuccess &&
            cudaEventCreateWithFlags(&g_fork, cudaEventDisableTiming) == cudaSuccess &&
            cudaEventCreateWithFlags(&g_join, cudaEventDisableTiming) == cudaSuccess) {
            g_ready = 1;
        } else {
            g_ready = -1;
        }
    }

    if (g_ready == 1 && n_copy > 0 && n_zero > 0) {
        // fork point
        cudaEventRecord(g_fork, 0);

        // long pole first: memset node on the main (capture) stream
        cudaMemsetAsync(out + n_copy, 0, (size_t)n_zero * sizeof(float), 0);

        // copy branch on the side stream, forked from the same point
        cudaStreamWaitEvent(g_side, g_fork, 0);
        cudaMemcpyAsync(out, hidden, (size_t)n_copy * sizeof(float),
                        cudaMemcpyDeviceToDevice, g_side);
        cudaEventRecord(g_join, g_side);

        // join: main stream waits for the copy branch
        cudaStreamWaitEvent(0, g_join, 0);
    } else {
        // serial fallback (proven R3 path)
        if (n_copy > 0) {
            cudaMemcpyAsync(out, hidden, (size_t)n_copy * sizeof(float),
                            cudaMemcpyDeviceToDevice, 0);
        }
        if (n_zero > 0) {
            cudaMemsetAsync(out + n_copy, 0, (size_t)n_zero * sizeof(float), 0);
        }
    }
}